// round 14
// baseline (speedup 1.0000x reference)
#include <cuda_runtime.h>

// ---------------------------------------------------------------------------
// OmniSuperPointTransformer: gather + pos-MLP (3->32 LN ReLU 32->32) +
// fused segment-mean scatter into superpoints.
//
//  * W2 commutes with segment-sum -> matmul once per superpoint (finalize).
//  * Warp-cooperative points (lane = channel): coalesced gather + scatter.
//  * LN variance as a precomputed QUADRATIC FORM in (x,y,z,1):
//    var*32 = p^T M p, M = sum_c w_c w_c^T (10 coeffs) -> kills the 5-deep
//    serial SHFL butterfly (~150 cyc/point) entirely.
//  * Depth-8 gather prefetch ring issued BEFORE the red.* instructions
//    (their asm memory clobber is a compiler barrier that was pinning the
//    gather at MLP=1).
//  * pre-centered LayerNorm weights; accumulator [64 interleaved | xyz cnt]
//    = 68 f32/sp (13.6 MB, L2-resident REDs).
// ---------------------------------------------------------------------------

#define N_SP_MAX   50000
#define ACC_STRIDE 68
#define LN_EPS     1e-5f
#define FULLMASK   0xffffffffu

__device__ __align__(16) float g_acc[N_SP_MAX * ACC_STRIDE];
__device__ __align__(16) float g_W1c[96];
__device__ __align__(16) float g_b1c[32];
__device__ __align__(16) float g_Q[12];     // 10 quad-form coeffs (padded)

__global__ void osp_zero_kernel(int n4) {
    int i = blockIdx.x * blockDim.x + threadIdx.x;
    if (i < n4) reinterpret_cast<float4*>(g_acc)[i] = make_float4(0.f, 0.f, 0.f, 0.f);
}

// Center W1/b1 (so Linear(3,32) output is zero-mean) AND build the
// variance quadratic form: var*32 = qxx x^2 + qyy y^2 + qzz z^2
//   + qxy xy + qxz xz + qyz yz + qx x + qy y + qz z + qc   (cross terms
//   already doubled in the stored coefficients).
__global__ void osp_center_kernel(const float* __restrict__ W1,
                                  const float* __restrict__ b1) {
    __shared__ float m[4];
    __shared__ float cw[128];          // [x|y|z|b] centered, 32 each
    int c = threadIdx.x;               // 32 threads
    if (c < 3) {
        float s = 0.f;
        for (int j = 0; j < 32; j++) s += W1[c * 32 + j];
        m[c] = s * (1.f / 32.f);
    } else if (c == 3) {
        float s = 0.f;
        for (int j = 0; j < 32; j++) s += b1[j];
        m[3] = s * (1.f / 32.f);
    }
    __syncthreads();
    float wx = W1[0 * 32 + c] - m[0];
    float wy = W1[1 * 32 + c] - m[1];
    float wz = W1[2 * 32 + c] - m[2];
    float bb = b1[c] - m[3];
    g_W1c[0 * 32 + c] = wx;  cw[0 * 32 + c] = wx;
    g_W1c[1 * 32 + c] = wy;  cw[1 * 32 + c] = wy;
    g_W1c[2 * 32 + c] = wz;  cw[2 * 32 + c] = wz;
    g_b1c[c]          = bb;  cw[3 * 32 + c] = bb;
    __syncthreads();
    if (c < 10) {
        const int A[10] = {0, 1, 2, 0, 0, 1, 0, 1, 2, 3};
        const int B[10] = {0, 1, 2, 1, 2, 2, 3, 3, 3, 3};
        float s = 0.f;
        for (int j = 0; j < 32; j++) s += cw[A[c] * 32 + j] * cw[B[c] * 32 + j];
        g_Q[c] = (A[c] == B[c]) ? s : 2.f * s;
    }
}

__device__ __forceinline__ void red_add_v2(float* addr, float a, float b) {
    asm volatile("red.global.add.v2.f32 [%0], {%1, %2};"
                 :: "l"(addr), "f"(a), "f"(b) : "memory");
}
__device__ __forceinline__ void red_add_v4(float* addr, float a, float b, float c, float d) {
    asm volatile("red.global.add.v4.f32 [%0], {%1, %2, %3, %4};"
                 :: "l"(addr), "f"(a), "f"(b), "f"(c), "f"(d) : "memory");
}

// ---------------------------------------------------------------------------
// One WARP processes 32 consecutive points; lane = channel.
__global__ __launch_bounds__(256)
void osp_point_kernel(const float* __restrict__ voxel_feats,
                      const float* __restrict__ xyz,
                      const float* __restrict__ gamma,
                      const float* __restrict__ beta,
                      const int*   __restrict__ p2v,
                      const int*   __restrict__ spid,
                      int n_points)
{
    int lane = threadIdx.x & 31;
    int warp = blockIdx.x * (blockDim.x >> 5) + (threadIdx.x >> 5);
    long long pbase = (long long)warp * 32;
    if (pbase >= n_points) return;

    // per-lane channel params (registers for the whole kernel)
    float w1x = g_W1c[lane], w1y = g_W1c[32 + lane], w1z = g_W1c[64 + lane];
    float b1c = g_b1c[lane];
    float gc  = gamma[lane], btc = beta[lane];
    // quad-form coeffs (broadcast, once per warp)
    float q0 = g_Q[0], q1 = g_Q[1], q2 = g_Q[2], q3 = g_Q[3], q4 = g_Q[4];
    float q5 = g_Q[5], q6 = g_Q[6], q7 = g_Q[7], q8 = g_Q[8], q9 = g_Q[9];

    long long rem = (long long)n_points - pbase;
    int nIter = rem >= 32 ? 32 : (int)rem;

    // coalesced preload of this warp's 32 points: indices + xyz
    int pi = (int)pbase + lane;
    int v_l = 0, sp_l = 0;
    float x0 = 0.f, x1 = 0.f, x2 = 0.f;
    {
        if (lane < nIter) { v_l = p2v[pi]; sp_l = spid[pi]; }
        const float* xb = xyz + pbase * 3;
        int xn = nIter * 3;
        if (lane      < xn) x0 = xb[lane];
        if (32 + lane < xn) x1 = xb[32 + lane];
        if (64 + lane < xn) x2 = xb[64 + lane];
    }

    // depth-8 prefetch ring for the voxel gather
    float pf[8];
#pragma unroll
    for (int j = 0; j < 8; j++) {
        int vj = __shfl_sync(FULLMASK, v_l, j);
        pf[j] = (j < nIter) ? __ldg(voxel_feats + (size_t)vj * 32 + lane) : 0.f;
    }

#pragma unroll 8
    for (int t = 0; t < 32; t++) {
        if (t >= nIter) break;

        float fc = pf[t & 7];
        int sp = __shfl_sync(FULLMASK, sp_l, t);

        int ix = 3 * t;
        float px = __shfl_sync(FULLMASK, (ix     < 32) ? x0 : ((ix     < 64) ? x1 : x2), ix       & 31);
        float py = __shfl_sync(FULLMASK, (ix + 1 < 32) ? x0 : ((ix + 1 < 64) ? x1 : x2), (ix + 1) & 31);
        float pz = __shfl_sync(FULLMASK, (ix + 2 < 32) ? x0 : ((ix + 2 < 64) ? x1 : x2), (ix + 2) & 31);

        // issue next gather BEFORE the red barrier below (keeps MLP~8)
        int tn = t + 8;
        if (tn < nIter) {
            int vn = __shfl_sync(FULLMASK, v_l, tn);
            pf[t & 7] = __ldg(voxel_feats + (size_t)vn * 32 + lane);
        }

        // h per lane (pre-centered weights -> zero-mean)
        float h = fmaf(px, w1x, fmaf(py, w1y, fmaf(pz, w1z, b1c)));

        // variance via quadratic form (lane-local, no shuffles)
        float ta = fmaf(q3, py, fmaf(q4, pz, q6));  ta = fmaf(q0, px, ta);
        float tb = fmaf(q1, py, fmaf(q5, pz, q7));
        float tc = fmaf(q2, pz, q8);
        float v32 = fmaf(px, ta, fmaf(py, tb, fmaf(pz, tc, q9)));
        float inv = rsqrtf(fmaf(v32, (1.f / 32.f), LN_EPS));
        float r = fmaxf(fmaf(h * inv, gc, btc), 0.f);

        // coalesced scatter: lane c -> 8B at base+8c (contiguous 256B row)
        float* base = g_acc + (size_t)sp * ACC_STRIDE;
        red_add_v2(base + 2 * lane, fc, r);
        if (lane == 0) red_add_v4(base + 64, px, py, pz, 1.0f);
    }
}

// ---------------------------------------------------------------------------
// One WARP per superpoint; 2-way split FMA chains.
__global__ __launch_bounds__(256)
void osp_finalize_kernel(float* __restrict__ out,
                         const float* __restrict__ W2,
                         const float* __restrict__ b2,
                         int S)
{
    __shared__ __align__(16) float sW2[1024];
    for (int t = threadIdx.x; t < 1024; t += blockDim.x) sW2[t] = W2[t];
    __syncthreads();

    int lane = threadIdx.x & 31;
    int sp = blockIdx.x * (blockDim.x >> 5) + (threadIdx.x >> 5);
    if (sp >= S) return;

    const float* base = g_acc + (size_t)sp * ACC_STRIDE;
    float2 fr = reinterpret_cast<const float2*>(base)[lane];   // (feat_c, relu_c)
    float cnt = base[67];
    float den = fmaxf(cnt, 1.0f);
    float rinv = 1.0f / den;

    float r = fr.y;
    float oa = fmaf(cnt, b2[lane], fr.x);
    float ob = 0.f;
#pragma unroll
    for (int k = 0; k < 32; k += 2) {
        float a0 = __shfl_sync(FULLMASK, r, k);
        float a1 = __shfl_sync(FULLMASK, r, k + 1);
        oa = fmaf(a0, sW2[k * 32 + lane], oa);
        ob = fmaf(a1, sW2[(k + 1) * 32 + lane], ob);
    }

    out[(size_t)sp * 32 + lane] = (oa + ob) * rinv;
    if (lane < 3)
        out[(size_t)S * 32 + (size_t)sp * 3 + lane] = base[64 + lane] * rinv;
}

// ---------------------------------------------------------------------------
extern "C" void kernel_launch(void* const* d_in, const int* in_sizes, int n_in,
                              void* d_out, int out_size)
{
    const float* voxel_feats = (const float*)d_in[0];
    const float* xyz         = (const float*)d_in[1];
    const float* W1          = (const float*)d_in[2];
    const float* b1          = (const float*)d_in[3];
    const float* gamma       = (const float*)d_in[4];
    const float* beta        = (const float*)d_in[5];
    const float* W2          = (const float*)d_in[6];
    const float* b2          = (const float*)d_in[7];
    const int*   p2v         = (const int*)d_in[8];
    const int*   spid        = (const int*)d_in[9];

    int n_points = in_sizes[8];
    int S        = out_size / 35;
    if (S > N_SP_MAX) S = N_SP_MAX;

    int n4 = (S * ACC_STRIDE) / 4;       // 68 % 4 == 0
    osp_zero_kernel<<<(n4 + 255) / 256, 256>>>(n4);
    osp_center_kernel<<<1, 32>>>(W1, b1);

    int warps = (n_points + 31) / 32;            // one warp per 32 points
    int blocks = (warps + 7) / 8;                // 8 warps / 256-thread block
    osp_point_kernel<<<blocks, 256>>>(
        voxel_feats, xyz, gamma, beta, p2v, spid, n_points);

    int fblocks = (S + 7) / 8;                   // one warp per superpoint
    osp_finalize_kernel<<<fblocks, 256>>>((float*)d_out, W2, b2, S);
}

// round 15
// speedup vs baseline: 1.4144x; 1.4144x over previous
#include <cuda_runtime.h>

// ---------------------------------------------------------------------------
// OmniSuperPointTransformer: gather + pos-MLP (3->32 LN ReLU 32->32) +
// fused segment-mean scatter into superpoints.
//
//  * W2 commutes with segment-sum -> matmul once per superpoint (finalize).
//  * Warp-cooperative points (lane = channel): coalesced gather + scatter.
//  * LN variance as precomputed QUADRATIC FORM in (x,y,z,1):
//    var*32 = p^T M p, M = sum_c w_c w_c^T (10 coeffs) -> replaces the
//    5-deep serial SHFL butterfly with ~10 lane-local FMAs. (R14's prefetch
//    ring is REVERTED: pf[t&7] under partial unroll+break spilled to LMEM.)
//  * pre-centered LayerNorm weights; accumulator [64 interleaved | xyz cnt]
//    = 68 f32/sp (13.6 MB, L2-resident REDs).
// ---------------------------------------------------------------------------

#define N_SP_MAX   50000
#define ACC_STRIDE 68
#define LN_EPS     1e-5f
#define FULLMASK   0xffffffffu

__device__ __align__(16) float g_acc[N_SP_MAX * ACC_STRIDE];
__device__ __align__(16) float g_W1c[96];
__device__ __align__(16) float g_b1c[32];
__device__ __align__(16) float g_Q[12];     // 10 quad-form coeffs (padded)

__global__ void osp_zero_kernel(int n4) {
    int i = blockIdx.x * blockDim.x + threadIdx.x;
    if (i < n4) reinterpret_cast<float4*>(g_acc)[i] = make_float4(0.f, 0.f, 0.f, 0.f);
}

// Center W1/b1 (so Linear(3,32) output is zero-mean) AND build the variance
// quadratic form: var*32 = q0 x^2 + q1 y^2 + q2 z^2 + q3 xy + q4 xz + q5 yz
//                        + q6 x + q7 y + q8 z + q9  (cross terms pre-doubled).
__global__ void osp_center_kernel(const float* __restrict__ W1,
                                  const float* __restrict__ b1) {
    __shared__ float m[4];
    __shared__ float cw[128];          // [x|y|z|b] centered, 32 each
    int c = threadIdx.x;               // 32 threads
    if (c < 3) {
        float s = 0.f;
        for (int j = 0; j < 32; j++) s += W1[c * 32 + j];
        m[c] = s * (1.f / 32.f);
    } else if (c == 3) {
        float s = 0.f;
        for (int j = 0; j < 32; j++) s += b1[j];
        m[3] = s * (1.f / 32.f);
    }
    __syncthreads();
    float wx = W1[0 * 32 + c] - m[0];
    float wy = W1[1 * 32 + c] - m[1];
    float wz = W1[2 * 32 + c] - m[2];
    float bb = b1[c] - m[3];
    g_W1c[0 * 32 + c] = wx;  cw[0 * 32 + c] = wx;
    g_W1c[1 * 32 + c] = wy;  cw[1 * 32 + c] = wy;
    g_W1c[2 * 32 + c] = wz;  cw[2 * 32 + c] = wz;
    g_b1c[c]          = bb;  cw[3 * 32 + c] = bb;
    __syncthreads();
    if (c < 10) {
        const int A[10] = {0, 1, 2, 0, 0, 1, 0, 1, 2, 3};
        const int B[10] = {0, 1, 2, 1, 2, 2, 3, 3, 3, 3};
        float s = 0.f;
        for (int j = 0; j < 32; j++) s += cw[A[c] * 32 + j] * cw[B[c] * 32 + j];
        g_Q[c] = (A[c] == B[c]) ? s : 2.f * s;
    }
}

__device__ __forceinline__ void red_add_v2(float* addr, float a, float b) {
    asm volatile("red.global.add.v2.f32 [%0], {%1, %2};"
                 :: "l"(addr), "f"(a), "f"(b) : "memory");
}
__device__ __forceinline__ void red_add_v4(float* addr, float a, float b, float c, float d) {
    asm volatile("red.global.add.v4.f32 [%0], {%1, %2, %3, %4};"
                 :: "l"(addr), "f"(a), "f"(b), "f"(c), "f"(d) : "memory");
}

// ---------------------------------------------------------------------------
// One WARP processes 32 consecutive points; lane = channel.  (R13 structure.)
__global__ __launch_bounds__(256)
void osp_point_kernel(const float* __restrict__ voxel_feats,
                      const float* __restrict__ xyz,
                      const float* __restrict__ gamma,
                      const float* __restrict__ beta,
                      const int*   __restrict__ p2v,
                      const int*   __restrict__ spid,
                      int n_points)
{
    int lane = threadIdx.x & 31;
    int warp = blockIdx.x * (blockDim.x >> 5) + (threadIdx.x >> 5);
    long long pbase = (long long)warp * 32;
    if (pbase >= n_points) return;

    // per-lane channel parameters (registers for the whole kernel)
    float w1x = g_W1c[lane], w1y = g_W1c[32 + lane], w1z = g_W1c[64 + lane];
    float b1c = g_b1c[lane];
    float gc  = gamma[lane], btc = beta[lane];
    // quad-form coeffs (uniform across warp)
    float q0 = g_Q[0], q1 = g_Q[1], q2 = g_Q[2], q3 = g_Q[3], q4 = g_Q[4];
    float q5 = g_Q[5], q6 = g_Q[6], q7 = g_Q[7], q8 = g_Q[8], q9 = g_Q[9];

    bool full = (pbase + 32 <= (long long)n_points);
    int nIter = full ? 32 : (int)((long long)n_points - pbase);

    // coalesced preload of this warp's 32 points: indices + xyz (96 floats)
    int pi = (int)pbase + lane;
    int v_l = 0, sp_l = 0;
    float x0 = 0.f, x1 = 0.f, x2 = 0.f;
    if (full) {
        v_l  = p2v[pi];
        sp_l = spid[pi];
        const float* xb = xyz + pbase * 3;
        x0 = xb[lane]; x1 = xb[32 + lane]; x2 = xb[64 + lane];
    } else {
        if (lane < nIter) { v_l = p2v[pi]; sp_l = spid[pi]; }
        int xn = nIter * 3;
        const float* xb = xyz + pbase * 3;
        if (lane      < xn) x0 = xb[lane];
        if (32 + lane < xn) x1 = xb[32 + lane];
        if (64 + lane < xn) x2 = xb[64 + lane];
    }

#pragma unroll 4
    for (int t = 0; t < 32; t++) {
        if (t >= nIter) break;

        int v  = __shfl_sync(FULLMASK, v_l,  t);
        int sp = __shfl_sync(FULLMASK, sp_l, t);

        int ix = 3 * t;            // xyz element indices 3t, 3t+1, 3t+2
        float px = __shfl_sync(FULLMASK, (ix      < 32) ? x0 : ((ix      < 64) ? x1 : x2), ix      & 31);
        float py = __shfl_sync(FULLMASK, (ix + 1  < 32) ? x0 : ((ix + 1  < 64) ? x1 : x2), (ix + 1) & 31);
        float pz = __shfl_sync(FULLMASK, (ix + 2  < 32) ? x0 : ((ix + 2  < 64) ? x1 : x2), (ix + 2) & 31);

        // coalesced gather: one 128B line for this point's voxel row
        float fc = __ldg(voxel_feats + (size_t)v * 32 + lane);

        // h per lane (pre-centered weights -> zero-mean over channels)
        float h = fmaf(px, w1x, fmaf(py, w1y, fmaf(pz, w1z, b1c)));

        // variance via quadratic form (lane-local; replaces SHFL butterfly)
        float ta = fmaf(q3, py, fmaf(q4, pz, q6));  ta = fmaf(q0, px, ta);
        float tb = fmaf(q1, py, fmaf(q5, pz, q7));
        float tc = fmaf(q2, pz, q8);
        float v32 = fmaf(px, ta, fmaf(py, tb, fmaf(pz, tc, q9)));
        float inv = rsqrtf(fmaf(v32, (1.f / 32.f), LN_EPS));
        float r = fmaxf(fmaf(h * inv, gc, btc), 0.f);

        // coalesced scatter: lane c -> 8B at base+8c (contiguous 256B row)
        float* base = g_acc + (size_t)sp * ACC_STRIDE;
        red_add_v2(base + 2 * lane, fc, r);
        if (lane == 0) red_add_v4(base + 64, px, py, pz, 1.0f);
    }
}

// ---------------------------------------------------------------------------
// One WARP per superpoint: o[c] = (accF[c] + sum_k accR[k]*W2[k][c] + cnt*b2[c]) / den
__global__ __launch_bounds__(256)
void osp_finalize_kernel(float* __restrict__ out,
                         const float* __restrict__ W2,
                         const float* __restrict__ b2,
                         int S)
{
    __shared__ __align__(16) float sW2[1024];
    for (int t = threadIdx.x; t < 1024; t += blockDim.x) sW2[t] = W2[t];
    __syncthreads();

    int lane = threadIdx.x & 31;
    int sp = blockIdx.x * (blockDim.x >> 5) + (threadIdx.x >> 5);
    if (sp >= S) return;

    const float* base = g_acc + (size_t)sp * ACC_STRIDE;
    float2 fr = reinterpret_cast<const float2*>(base)[lane];   // (feat_c, relu_c)
    float cnt = base[67];
    float den = fmaxf(cnt, 1.0f);
    float rinv = 1.0f / den;

    float o = fmaf(cnt, b2[lane], fr.x);
    float r = fr.y;
#pragma unroll
    for (int k = 0; k < 32; k++) {
        float a = __shfl_sync(FULLMASK, r, k);
        o = fmaf(a, sW2[k * 32 + lane], o);
    }

    out[(size_t)sp * 32 + lane] = o * rinv;
    if (lane < 3)
        out[(size_t)S * 32 + (size_t)sp * 3 + lane] = base[64 + lane] * rinv;
}

// ---------------------------------------------------------------------------
extern "C" void kernel_launch(void* const* d_in, const int* in_sizes, int n_in,
                              void* d_out, int out_size)
{
    const float* voxel_feats = (const float*)d_in[0];
    const float* xyz         = (const float*)d_in[1];
    const float* W1          = (const float*)d_in[2];
    const float* b1          = (const float*)d_in[3];
    const float* gamma       = (const float*)d_in[4];
    const float* beta        = (const float*)d_in[5];
    const float* W2          = (const float*)d_in[6];
    const float* b2          = (const float*)d_in[7];
    const int*   p2v         = (const int*)d_in[8];
    const int*   spid        = (const int*)d_in[9];

    int n_points = in_sizes[8];
    int S        = out_size / 35;
    if (S > N_SP_MAX) S = N_SP_MAX;

    int n4 = (S * ACC_STRIDE) / 4;       // 68 % 4 == 0
    osp_zero_kernel<<<(n4 + 255) / 256, 256>>>(n4);
    osp_center_kernel<<<1, 32>>>(W1, b1);

    int warps = (n_points + 31) / 32;            // one warp per 32 points
    int blocks = (warps + 7) / 8;                // 8 warps / 256-thread block
    osp_point_kernel<<<blocks, 256>>>(
        voxel_feats, xyz, gamma, beta, p2v, spid, n_points);

    int fblocks = (S + 7) / 8;                   // one warp per superpoint
    osp_finalize_kernel<<<fblocks, 256>>>((float*)d_out, W2, b2, S);
}

// round 16
// speedup vs baseline: 1.8059x; 1.2768x over previous
#include <cuda_runtime.h>

// ---------------------------------------------------------------------------
// OmniSuperPointTransformer: gather + pos-MLP (3->32 LN ReLU 32->32) +
// fused segment-mean scatter into superpoints.
//
//  * W2 commutes with segment-sum -> matmul once per superpoint (finalize).
//  * Warp-cooperative points (lane = channel): coalesced gather + scatter.
//  * LN variance as precomputed quadratic form in (x,y,z,1) (10 coeffs).
//  * BATCH-4 SOFTWARE PIPELINE: the red.* asm has a "memory" clobber, which
//    forbids hoisting the next gather LDG above the previous RED -> MLP=1.
//    Batching 4 points with NAMED scalar registers (full unroll, no dynamic
//    indexing -> no LMEM, unlike R14's ring) issues 4 LDGs before the first
//    RED of the batch -> MLP=4, ~4x less exposed DRAM latency per warp.
//  * pre-centered LayerNorm weights; accumulator [64 interleaved | xyz cnt]
//    = 68 f32/sp (13.6 MB, L2-resident REDs).
// ---------------------------------------------------------------------------

#define N_SP_MAX   50000
#define ACC_STRIDE 68
#define LN_EPS     1e-5f
#define FULLMASK   0xffffffffu

__device__ __align__(16) float g_acc[N_SP_MAX * ACC_STRIDE];
__device__ __align__(16) float g_W1c[96];
__device__ __align__(16) float g_b1c[32];
__device__ __align__(16) float g_Q[12];

__global__ void osp_zero_kernel(int n4) {
    int i = blockIdx.x * blockDim.x + threadIdx.x;
    if (i < n4) reinterpret_cast<float4*>(g_acc)[i] = make_float4(0.f, 0.f, 0.f, 0.f);
}

// Center W1/b1 and build variance quad form:
// var*32 = q0 x^2 + q1 y^2 + q2 z^2 + q3 xy + q4 xz + q5 yz
//        + q6 x + q7 y + q8 z + q9   (cross terms pre-doubled).
__global__ void osp_center_kernel(const float* __restrict__ W1,
                                  const float* __restrict__ b1) {
    __shared__ float m[4];
    __shared__ float cw[128];
    int c = threadIdx.x;               // 32 threads
    if (c < 3) {
        float s = 0.f;
        for (int j = 0; j < 32; j++) s += W1[c * 32 + j];
        m[c] = s * (1.f / 32.f);
    } else if (c == 3) {
        float s = 0.f;
        for (int j = 0; j < 32; j++) s += b1[j];
        m[3] = s * (1.f / 32.f);
    }
    __syncthreads();
    float wx = W1[0 * 32 + c] - m[0];
    float wy = W1[1 * 32 + c] - m[1];
    float wz = W1[2 * 32 + c] - m[2];
    float bb = b1[c] - m[3];
    g_W1c[0 * 32 + c] = wx;  cw[0 * 32 + c] = wx;
    g_W1c[1 * 32 + c] = wy;  cw[1 * 32 + c] = wy;
    g_W1c[2 * 32 + c] = wz;  cw[2 * 32 + c] = wz;
    g_b1c[c]          = bb;  cw[3 * 32 + c] = bb;
    __syncthreads();
    if (c < 10) {
        const int A[10] = {0, 1, 2, 0, 0, 1, 0, 1, 2, 3};
        const int B[10] = {0, 1, 2, 1, 2, 2, 3, 3, 3, 3};
        float s = 0.f;
        for (int j = 0; j < 32; j++) s += cw[A[c] * 32 + j] * cw[B[c] * 32 + j];
        g_Q[c] = (A[c] == B[c]) ? s : 2.f * s;
    }
}

__device__ __forceinline__ void red_add_v2(float* addr, float a, float b) {
    asm volatile("red.global.add.v2.f32 [%0], {%1, %2};"
                 :: "l"(addr), "f"(a), "f"(b) : "memory");
}
__device__ __forceinline__ void red_add_v4(float* addr, float a, float b, float c, float d) {
    asm volatile("red.global.add.v4.f32 [%0], {%1, %2, %3, %4};"
                 :: "l"(addr), "f"(a), "f"(b), "f"(c), "f"(d) : "memory");
}

// ---------------------------------------------------------------------------
// One WARP processes 32 consecutive points; lane = channel.
__global__ __launch_bounds__(256)
void osp_point_kernel(const float* __restrict__ voxel_feats,
                      const float* __restrict__ xyz,
                      const float* __restrict__ gamma,
                      const float* __restrict__ beta,
                      const int*   __restrict__ p2v,
                      const int*   __restrict__ spid,
                      int n_points)
{
    int lane = threadIdx.x & 31;
    int warp = blockIdx.x * (blockDim.x >> 5) + (threadIdx.x >> 5);
    long long pbase = (long long)warp * 32;
    if (pbase >= n_points) return;

    float w1x = g_W1c[lane], w1y = g_W1c[32 + lane], w1z = g_W1c[64 + lane];
    float b1c = g_b1c[lane];
    float gc  = gamma[lane], btc = beta[lane];
    float q0 = g_Q[0], q1 = g_Q[1], q2 = g_Q[2], q3 = g_Q[3], q4 = g_Q[4];
    float q5 = g_Q[5], q6 = g_Q[6], q7 = g_Q[7], q8 = g_Q[8], q9 = g_Q[9];

    bool full = (pbase + 32 <= (long long)n_points);
    int nIter = full ? 32 : (int)((long long)n_points - pbase);

    // coalesced preload: indices + xyz (transposed in 3 lane-registers)
    int pi = (int)pbase + lane;
    int v_l = 0, sp_l = 0;
    float x0 = 0.f, x1 = 0.f, x2 = 0.f;
    if (full) {
        v_l  = p2v[pi];
        sp_l = spid[pi];
        const float* xb = xyz + pbase * 3;
        x0 = xb[lane]; x1 = xb[32 + lane]; x2 = xb[64 + lane];
    } else {
        if (lane < nIter) { v_l = p2v[pi]; sp_l = spid[pi]; }
        int xn = nIter * 3;
        const float* xb = xyz + pbase * 3;
        if (lane      < xn) x0 = xb[lane];
        if (32 + lane < xn) x1 = xb[32 + lane];
        if (64 + lane < xn) x2 = xb[64 + lane];
    }

    // xyz element e (0..95): e<32 -> x0, e<64 -> x1, else x2; source lane e&31.
    // All e are compile-time constants in the unrolled path.
#define XYZ_ELT(e) __shfl_sync(FULLMASK, ((e) < 32) ? x0 : (((e) < 64) ? x1 : x2), (e) & 31)

    if (full) {
#pragma unroll
        for (int b = 0; b < 8; b++) {
            const int t0 = 4 * b;

            // ---- phase 1: 4 gathers in flight BEFORE any RED of this batch
            int v0 = __shfl_sync(FULLMASK, v_l, t0 + 0);
            int v1 = __shfl_sync(FULLMASK, v_l, t0 + 1);
            int v2 = __shfl_sync(FULLMASK, v_l, t0 + 2);
            int v3 = __shfl_sync(FULLMASK, v_l, t0 + 3);
            float f0 = __ldg(voxel_feats + (size_t)v0 * 32 + lane);
            float f1 = __ldg(voxel_feats + (size_t)v1 * 32 + lane);
            float f2 = __ldg(voxel_feats + (size_t)v2 * 32 + lane);
            float f3 = __ldg(voxel_feats + (size_t)v3 * 32 + lane);

            int s0 = __shfl_sync(FULLMASK, sp_l, t0 + 0);
            int s1 = __shfl_sync(FULLMASK, sp_l, t0 + 1);
            int s2 = __shfl_sync(FULLMASK, sp_l, t0 + 2);
            int s3 = __shfl_sync(FULLMASK, sp_l, t0 + 3);

            float px0 = XYZ_ELT(3 * (t0 + 0) + 0), py0 = XYZ_ELT(3 * (t0 + 0) + 1), pz0 = XYZ_ELT(3 * (t0 + 0) + 2);
            float px1 = XYZ_ELT(3 * (t0 + 1) + 0), py1 = XYZ_ELT(3 * (t0 + 1) + 1), pz1 = XYZ_ELT(3 * (t0 + 1) + 2);
            float px2 = XYZ_ELT(3 * (t0 + 2) + 0), py2 = XYZ_ELT(3 * (t0 + 2) + 1), pz2 = XYZ_ELT(3 * (t0 + 2) + 2);
            float px3 = XYZ_ELT(3 * (t0 + 3) + 0), py3 = XYZ_ELT(3 * (t0 + 3) + 1), pz3 = XYZ_ELT(3 * (t0 + 3) + 2);

            // ---- phase 2: MLP + LN(quad form) + ReLU for 4 points
#define COMPUTE_R(px, py, pz, rr)                                              \
            {                                                                  \
                float h = fmaf(px, w1x, fmaf(py, w1y, fmaf(pz, w1z, b1c)));    \
                float ta = fmaf(q3, py, fmaf(q4, pz, q6)); ta = fmaf(q0, px, ta); \
                float tb = fmaf(q1, py, fmaf(q5, pz, q7));                     \
                float tc = fmaf(q2, pz, q8);                                   \
                float v32 = fmaf(px, ta, fmaf(py, tb, fmaf(pz, tc, q9)));      \
                float inv = rsqrtf(fmaf(v32, (1.f / 32.f), LN_EPS));           \
                rr = fmaxf(fmaf(h * inv, gc, btc), 0.f);                       \
            }
            float r0, r1, r2, r3;
            COMPUTE_R(px0, py0, pz0, r0)
            COMPUTE_R(px1, py1, pz1, r1)
            COMPUTE_R(px2, py2, pz2, r2)
            COMPUTE_R(px3, py3, pz3, r3)
#undef COMPUTE_R

            // ---- phase 3: scatter (coalesced 256B rows)
            float* a0 = g_acc + (size_t)s0 * ACC_STRIDE;
            float* a1 = g_acc + (size_t)s1 * ACC_STRIDE;
            float* a2 = g_acc + (size_t)s2 * ACC_STRIDE;
            float* a3 = g_acc + (size_t)s3 * ACC_STRIDE;
            red_add_v2(a0 + 2 * lane, f0, r0);
            red_add_v2(a1 + 2 * lane, f1, r1);
            red_add_v2(a2 + 2 * lane, f2, r2);
            red_add_v2(a3 + 2 * lane, f3, r3);
            if (lane == 0) {
                red_add_v4(a0 + 64, px0, py0, pz0, 1.0f);
                red_add_v4(a1 + 64, px1, py1, pz1, 1.0f);
                red_add_v4(a2 + 64, px2, py2, pz2, 1.0f);
                red_add_v4(a3 + 64, px3, py3, pz3, 1.0f);
            }
        }
    } else {
        // tail warp: simple per-point loop (at most one warp in the grid)
        for (int t = 0; t < nIter; t++) {
            int v  = __shfl_sync(FULLMASK, v_l,  t);
            int sp = __shfl_sync(FULLMASK, sp_l, t);
            int ix = 3 * t;
            float px = __shfl_sync(FULLMASK, (ix     < 32) ? x0 : ((ix     < 64) ? x1 : x2), ix       & 31);
            float py = __shfl_sync(FULLMASK, (ix + 1 < 32) ? x0 : ((ix + 1 < 64) ? x1 : x2), (ix + 1) & 31);
            float pz = __shfl_sync(FULLMASK, (ix + 2 < 32) ? x0 : ((ix + 2 < 64) ? x1 : x2), (ix + 2) & 31);

            float fc = __ldg(voxel_feats + (size_t)v * 32 + lane);
            float h = fmaf(px, w1x, fmaf(py, w1y, fmaf(pz, w1z, b1c)));
            float ta = fmaf(q3, py, fmaf(q4, pz, q6));  ta = fmaf(q0, px, ta);
            float tb = fmaf(q1, py, fmaf(q5, pz, q7));
            float tc = fmaf(q2, pz, q8);
            float v32 = fmaf(px, ta, fmaf(py, tb, fmaf(pz, tc, q9)));
            float inv = rsqrtf(fmaf(v32, (1.f / 32.f), LN_EPS));
            float r = fmaxf(fmaf(h * inv, gc, btc), 0.f);

            float* base = g_acc + (size_t)sp * ACC_STRIDE;
            red_add_v2(base + 2 * lane, fc, r);
            if (lane == 0) red_add_v4(base + 64, px, py, pz, 1.0f);
        }
    }
#undef XYZ_ELT
}

// ---------------------------------------------------------------------------
// One WARP per superpoint: o[c] = (accF[c] + sum_k accR[k]*W2[k][c] + cnt*b2[c]) / den
__global__ __launch_bounds__(256)
void osp_finalize_kernel(float* __restrict__ out,
                         const float* __restrict__ W2,
                         const float* __restrict__ b2,
                         int S)
{
    __shared__ __align__(16) float sW2[1024];
    for (int t = threadIdx.x; t < 1024; t += blockDim.x) sW2[t] = W2[t];
    __syncthreads();

    int lane = threadIdx.x & 31;
    int sp = blockIdx.x * (blockDim.x >> 5) + (threadIdx.x >> 5);
    if (sp >= S) return;

    const float* base = g_acc + (size_t)sp * ACC_STRIDE;
    float2 fr = reinterpret_cast<const float2*>(base)[lane];   // (feat_c, relu_c)
    float cnt = base[67];
    float den = fmaxf(cnt, 1.0f);
    float rinv = 1.0f / den;

    float o = fmaf(cnt, b2[lane], fr.x);
    float r = fr.y;
#pragma unroll
    for (int k = 0; k < 32; k++) {
        float a = __shfl_sync(FULLMASK, r, k);
        o = fmaf(a, sW2[k * 32 + lane], o);
    }

    out[(size_t)sp * 32 + lane] = o * rinv;
    if (lane < 3)
        out[(size_t)S * 32 + (size_t)sp * 3 + lane] = base[64 + lane] * rinv;
}

// ---------------------------------------------------------------------------
extern "C" void kernel_launch(void* const* d_in, const int* in_sizes, int n_in,
                              void* d_out, int out_size)
{
    const float* voxel_feats = (const float*)d_in[0];
    const float* xyz         = (const float*)d_in[1];
    const float* W1          = (const float*)d_in[2];
    const float* b1          = (const float*)d_in[3];
    const float* gamma       = (const float*)d_in[4];
    const float* beta        = (const float*)d_in[5];
    const float* W2          = (const float*)d_in[6];
    const float* b2          = (const float*)d_in[7];
    const int*   p2v         = (const int*)d_in[8];
    const int*   spid        = (const int*)d_in[9];

    int n_points = in_sizes[8];
    int S        = out_size / 35;
    if (S > N_SP_MAX) S = N_SP_MAX;

    int n4 = (S * ACC_STRIDE) / 4;       // 68 % 4 == 0
    osp_zero_kernel<<<(n4 + 255) / 256, 256>>>(n4);
    osp_center_kernel<<<1, 32>>>(W1, b1);

    int warps = (n_points + 31) / 32;            // one warp per 32 points
    int blocks = (warps + 7) / 8;                // 8 warps / 256-thread block
    osp_point_kernel<<<blocks, 256>>>(
        voxel_feats, xyz, gamma, beta, p2v, spid, n_points);

    int fblocks = (S + 7) / 8;                   // one warp per superpoint
    osp_finalize_kernel<<<fblocks, 256>>>((float*)d_out, W2, b2, S);
}